// round 10
// baseline (speedup 1.0000x reference)
#include <cuda_runtime.h>
#include <cuda_fp16.h>
#include <cstdint>

// ============================ problem constants ============================
constexpr int E = 512, H = 8, S = 64, TM = 64;

// ============================ device scratch (weights only) ================
// per head: {q_hi, k_hi, v_hi} 64x64 fp16 [s][t] SW128 tiles (8KB each) = 24KB/head
__device__ __align__(1024) unsigned char g_wqkv[H * 3 * 8192];
// Wu_hi chunks: bidx = nh*8 + kc -> [64k x 256n] fp16 swz512, 32KB each (512KB total)
__device__ __align__(1024) unsigned char g_wub[16 * 32768];

// ============================ helpers ======================================
__device__ __forceinline__ uint32_t smem_u32(const void* p) {
    uint32_t a;
    asm("{ .reg .u64 t; cvta.to.shared.u64 t, %1; cvt.u32.u64 %0, t; }" : "=r"(a) : "l"(p));
    return a;
}
__host__ __device__ __forceinline__ uint32_t swz128(uint32_t o) { return o ^ ((o >> 3) & 0x70); }
__host__ __device__ __forceinline__ uint32_t swz512(uint32_t o) { return o ^ ((o >> 5) & 0x70); }

__device__ __forceinline__ void ldsm_x4(uint32_t (&r)[4], uint32_t a) {
    asm volatile("ldmatrix.sync.aligned.m8n8.x4.shared.b16 {%0,%1,%2,%3}, [%4];"
        : "=r"(r[0]), "=r"(r[1]), "=r"(r[2]), "=r"(r[3]) : "r"(a));
}
__device__ __forceinline__ void ldsm_x4t(uint32_t (&r)[4], uint32_t a) {
    asm volatile("ldmatrix.sync.aligned.m8n8.x4.trans.shared.b16 {%0,%1,%2,%3}, [%4];"
        : "=r"(r[0]), "=r"(r[1]), "=r"(r[2]), "=r"(r[3]) : "r"(a));
}
__device__ __forceinline__ void mma16816(float (&d)[4], const uint32_t (&a)[4],
                                         uint32_t b0, uint32_t b1) {
    asm volatile("mma.sync.aligned.m16n8k16.row.col.f32.f16.f16.f32 "
        "{%0,%1,%2,%3}, {%4,%5,%6,%7}, {%8,%9}, {%0,%1,%2,%3};"
        : "+f"(d[0]), "+f"(d[1]), "+f"(d[2]), "+f"(d[3])
        : "r"(a[0]), "r"(a[1]), "r"(a[2]), "r"(a[3]), "r"(b0), "r"(b1));
}
__device__ __forceinline__ void cp16(uint32_t dst, const void* src) {
    asm volatile("cp.async.cg.shared.global [%0], [%1], 16;" :: "r"(dst), "l"(src));
}
#define CP_COMMIT() asm volatile("cp.async.commit_group;" ::: "memory")
#define CP_WAIT(n)  asm volatile("cp.async.wait_group %0;" :: "n"(n) : "memory")

__device__ __forceinline__ uint32_t pack2h(__half a, __half b) {
    __half2 p(a, b);
    return *reinterpret_cast<uint32_t*>(&p);
}
__device__ __forceinline__ uint32_t packf2(float2 v) {
    return pack2h(__float2half(v.x), __float2half(v.y));
}

// ============================ prep kernels =================================
// mats: 0=q_hi, 1=k_hi, 2=v_hi ; tile layout [s-rows][t-cols] fp16 SW128
__global__ void prep_qkv(const float* __restrict__ Wq, const float* __restrict__ Wk,
                         const float* __restrict__ Wv) {
    int idx = blockIdx.x * 256 + threadIdx.x;
    if (idx >= H * 3 * S * S) return;
    int h = idx / (3 * S * S);
    int mat = (idx >> 12) % 3;
    int s = (idx >> 6) & 63, t = idx & 63;
    const float* W = (mat == 0) ? Wq : ((mat == 1) ? Wk : Wv);
    float v = W[(h * S + s) * S + t];
    uint32_t off = swz128((uint32_t)(s * 128 + t * 2));
    *reinterpret_cast<__half*>(g_wqkv + (size_t)(h * 3 + mat) * 8192 + off) = __float2half(v);
}
// Wu_hi: chunk bidx = (n>>8)*8 + (k>>6): [64k x 256n] fp16 swz512
__global__ void prep_wu(const float* __restrict__ Wu) {
    int idx = blockIdx.x * 256 + threadIdx.x;
    if (idx >= E * E) return;
    int k = idx >> 9, n = idx & 511;
    int kc = k >> 6, kk = k & 63, nh = n >> 8, nn = n & 255;
    size_t base = (size_t)(nh * 8 + kc) * 32768;
    uint32_t off = swz512((uint32_t)(kk * 512 + nn * 2));
    *reinterpret_cast<__half*>(g_wub + base + off) = __float2half(Wu[idx]);
}

// ============================ fused kernel =================================
// smem map (bytes), 112KB total -> 2 CTAs/SM:
//   sT  @ 0     : 8 tiles [64r x 64k] fp16 SW128 (head h = k-chunk h) = 64KB
//   BUF @ 65536 : phase1 = W head-pair (48KB); phase2 = B 3 x 16KB sub-chunks
constexpr uint32_t ST = 0, BUF = 65536;
constexpr uint32_t SMEM_TOTAL = 114688;

__global__ __launch_bounds__(256, 2)
void fused_sparse_attn(const float* __restrict__ x,
                       const float* __restrict__ bq, const float* __restrict__ bk,
                       const float* __restrict__ bv,
                       const float* __restrict__ bu, float* __restrict__ out)
{
    extern __shared__ unsigned char smem[];
    const uint32_t sb = smem_u32(smem);
    const int tid = threadIdx.x, lane = tid & 31, wid = tid >> 5;
    const int row0 = blockIdx.x * TM;
    const float SC = 0.04419417382415922f;   // 1/sqrt(512)

    const int g  = lane >> 2;
    const int qd = lane & 3;
    const uint32_t hiSel = (uint32_t)((lane >> 4) << 4);

    // ===================== Phase 1: QKV + softmax -> sT ====================
    const int lh = wid >> 2;                  // local head in pair
    const int wm = wid & 3;                   // 16-row m position

    auto load_W = [&](int hp) {
        const char* src = (const char*)g_wqkv + (size_t)hp * 49152;
        #pragma unroll
        for (int i = 0; i < 12; ++i) {
            uint32_t o = (uint32_t)(tid + i * 256) * 16;
            cp16(sb + BUF + o, src + o);
        }
        CP_COMMIT();
    };

    load_W(0);

    for (int hp = 0; hp < 4; ++hp) {
        // -- A fragments straight from gmem (overlaps the cp.async W load) --
        uint32_t aF[4][4];
        {
            const float* xr0 = x + (size_t)(row0 + wm * 16 + g) * E + hp * 128 + lh * 64;
            const float* xr1 = xr0 + 8 * (size_t)E;
            #pragma unroll
            for (int ks = 0; ks < 4; ++ks) {
                int c = ks * 16 + qd * 2;
                aF[ks][0] = packf2(*reinterpret_cast<const float2*>(xr0 + c));
                aF[ks][1] = packf2(*reinterpret_cast<const float2*>(xr1 + c));
                aF[ks][2] = packf2(*reinterpret_cast<const float2*>(xr0 + c + 8));
                aF[ks][3] = packf2(*reinterpret_cast<const float2*>(xr1 + c + 8));
            }
        }
        CP_WAIT(0);
        __syncthreads();          // W(hp) visible to all warps

        const int h = hp * 2 + lh;
        const uint32_t wbase = sb + BUF + (uint32_t)lh * 24576;

        float aq[8][4], ak[8][4];
        #pragma unroll
        for (int nt = 0; nt < 8; ++nt)
            #pragma unroll
            for (int c = 0; c < 4; ++c) { aq[nt][c] = 0.f; ak[nt][c] = 0.f; }

        // pass A: q and k
        #pragma unroll
        for (int ks = 0; ks < 4; ++ks) {
            #pragma unroll
            for (int ntp = 0; ntp < 4; ++ntp) {
                uint32_t boff = swz128((uint32_t)(ks * 16 + (lane & 15)) * 128
                                       + (uint32_t)ntp * 32 + hiSel);
                uint32_t bQ[4], bK[4];
                ldsm_x4t(bQ, wbase + boff);
                ldsm_x4t(bK, wbase + 8192 + boff);
                mma16816(aq[2*ntp],   aF[ks], bQ[0], bQ[1]);
                mma16816(aq[2*ntp+1], aF[ks], bQ[2], bQ[3]);
                mma16816(ak[2*ntp],   aF[ks], bK[0], bK[1]);
                mma16816(ak[2*ntp+1], aF[ks], bK[2], bK[3]);
            }
        }
        // pass B: v
        float av[8][4];
        #pragma unroll
        for (int nt = 0; nt < 8; ++nt)
            #pragma unroll
            for (int c = 0; c < 4; ++c) av[nt][c] = 0.f;
        #pragma unroll
        for (int ks = 0; ks < 4; ++ks) {
            #pragma unroll
            for (int ntp = 0; ntp < 4; ++ntp) {
                uint32_t boff = swz128((uint32_t)(ks * 16 + (lane & 15)) * 128
                                       + (uint32_t)ntp * 32 + hiSel);
                uint32_t bV[4];
                ldsm_x4t(bV, wbase + 16384 + boff);
                mma16816(av[2*ntp],   aF[ks], bV[0], bV[1]);
                mma16816(av[2*ntp+1], aF[ks], bV[2], bV[3]);
            }
        }

        __syncthreads();          // all warps done reading W(hp)
        if (hp < 3) load_W(hp + 1);   // overlap next W load with softmax+store

        // -- softmax (quad-local), reuse aq<-e, av<-v+bias --
        const float* bqh = bq + h * S;
        const float* bkh = bk + h * S;
        const float* bvh = bv + h * S;
        float ssum0 = 0.f, ssum1 = 0.f;
        #pragma unroll
        for (int nt = 0; nt < 8; ++nt) {
            int col0 = nt * 8 + qd * 2;
            float2 b1 = *reinterpret_cast<const float2*>(bqh + col0);
            float2 b2 = *reinterpret_cast<const float2*>(bkh + col0);
            float2 b3 = *reinterpret_cast<const float2*>(bvh + col0);
            float e;
            e = __expf((aq[nt][0] + b1.x) * (ak[nt][0] + b2.x) * SC); aq[nt][0] = e; ssum0 += e;
            e = __expf((aq[nt][1] + b1.y) * (ak[nt][1] + b2.y) * SC); aq[nt][1] = e; ssum0 += e;
            e = __expf((aq[nt][2] + b1.x) * (ak[nt][2] + b2.x) * SC); aq[nt][2] = e; ssum1 += e;
            e = __expf((aq[nt][3] + b1.y) * (ak[nt][3] + b2.y) * SC); aq[nt][3] = e; ssum1 += e;
            av[nt][0] += b3.x; av[nt][1] += b3.y;
            av[nt][2] += b3.x; av[nt][3] += b3.y;
        }
        ssum0 += __shfl_xor_sync(0xffffffffu, ssum0, 1);
        ssum0 += __shfl_xor_sync(0xffffffffu, ssum0, 2);
        ssum1 += __shfl_xor_sync(0xffffffffu, ssum1, 1);
        ssum1 += __shfl_xor_sync(0xffffffffu, ssum1, 2);
        const float inv0 = 1.0f / ssum0, inv1 = 1.0f / ssum1;

        {
            int rt0 = wm * 16 + g;
            #pragma unroll
            for (int nt = 0; nt < 8; ++nt) {
                uint32_t cb = (uint32_t)((nt * 8 + qd * 2) * 2);
                uint32_t offBase = (uint32_t)h * 8192;
                float t0 = aq[nt][0] * inv0 * av[nt][0];
                float t1 = aq[nt][1] * inv0 * av[nt][1];
                float t2 = aq[nt][2] * inv1 * av[nt][2];
                float t3 = aq[nt][3] * inv1 * av[nt][3];
                *reinterpret_cast<uint32_t*>(smem + ST + offBase
                    + swz128((uint32_t)rt0 * 128 + cb)) =
                    pack2h(__float2half(t0), __float2half(t1));
                *reinterpret_cast<uint32_t*>(smem + ST + offBase
                    + swz128((uint32_t)(rt0 + 8) * 128 + cb)) =
                    pack2h(__float2half(t2), __float2half(t3));
            }
        }
    }
    __syncthreads();              // sT coherent; BUF free for phase 2

    // ===================== Phase 2: out = t @ Wu_hi + bu ===================
    // warp = 32 rows x 64 cols: pm in {0,1}, pn in {0..3}; nh sweep over 2 halves
    // B sub-chunks 16KB, TRIPLE buffered, prefetch depth 2, CP_WAIT(1)
    const int pm = wid & 1;
    const int pn = wid >> 1;

    auto load_sub = [&](int s, int buf) {
        int nh = s >> 4, kc = (s >> 1) & 7, half = s & 1;
        const char* src = (const char*)g_wub + (size_t)(nh * 8 + kc) * 32768
                        + (size_t)half * 16384;
        uint32_t d = sb + BUF + (uint32_t)buf * 16384;
        #pragma unroll
        for (int i = 0; i < 4; ++i) {
            uint32_t o = (uint32_t)(tid + i * 256) * 16;
            cp16(d + o, src + o);
        }
        CP_COMMIT();
    };

    load_sub(0, 0);
    load_sub(1, 1);

    for (int nh = 0; nh < 2; ++nh) {
        float acc[16][4];
        #pragma unroll
        for (int nf = 0; nf < 16; ++nf)
            #pragma unroll
            for (int c = 0; c < 4; ++c) acc[nf][c] = 0.f;

        for (int s16 = 0; s16 < 16; ++s16) {
            int s = nh * 16 + s16;
            CP_WAIT(1);           // step-s load (issued 2 steps ago) complete
            __syncthreads();      // visible to all; buf (s+2)%3 free (read in s-1)
            if (s + 2 < 32) load_sub(s + 2, (s + 2) % 3);

            int kc = s16 >> 1, half = s16 & 1;
            uint32_t bb = sb + BUF + (uint32_t)(s % 3) * 16384;
            uint32_t tA = sb + ST + (uint32_t)kc * 8192;
            #pragma unroll
            for (int ksg = 0; ksg < 2; ++ksg) {
                uint32_t kOff = (uint32_t)(half * 64 + ksg * 32) + hiSel;
                uint32_t a0[4], a1[4];
                ldsm_x4(a0, tA + swz128((uint32_t)(pm * 32 + (lane & 15)) * 128 + kOff));
                ldsm_x4(a1, tA + swz128((uint32_t)(pm * 32 + 16 + (lane & 15)) * 128 + kOff));
                #pragma unroll
                for (int ntp = 0; ntp < 4; ++ntp) {
                    uint32_t boff = swz512((uint32_t)(ksg * 16 + (lane & 15)) * 512
                                           + (uint32_t)(pn * 128 + ntp * 32) + hiSel);
                    uint32_t b[4];
                    ldsm_x4t(b, bb + boff);
                    mma16816(acc[2*ntp],     a0, b[0], b[1]);
                    mma16816(acc[2*ntp+1],   a0, b[2], b[3]);
                    mma16816(acc[8+2*ntp],   a1, b[0], b[1]);
                    mma16816(acc[8+2*ntp+1], a1, b[2], b[3]);
                }
            }
        }

        // epilogue for this N-half (overlaps with in-flight prefetches)
        #pragma unroll
        for (int m = 0; m < 2; ++m) {
            int r0 = row0 + pm * 32 + m * 16 + g;
            #pragma unroll
            for (int nf = 0; nf < 8; ++nf) {
                int col0 = nh * 256 + pn * 64 + nf * 8 + qd * 2;
                float2 bb2 = *reinterpret_cast<const float2*>(bu + col0);
                const float* a = acc[m * 8 + nf];
                float2 o0 = make_float2(a[0] + bb2.x, a[1] + bb2.y);
                float2 o1 = make_float2(a[2] + bb2.x, a[3] + bb2.y);
                *reinterpret_cast<float2*>(out + (size_t)r0 * E + col0)       = o0;
                *reinterpret_cast<float2*>(out + (size_t)(r0 + 8) * E + col0) = o1;
            }
        }
    }
}

// ============================ launch =======================================
extern "C" void kernel_launch(void* const* d_in, const int* in_sizes, int n_in,
                              void* d_out, int out_size)
{
    const float* x  = (const float*)d_in[0];
    const float* Wq = (const float*)d_in[1];
    const float* bq = (const float*)d_in[2];
    const float* Wk = (const float*)d_in[3];
    const float* bk = (const float*)d_in[4];
    const float* Wv = (const float*)d_in[5];
    const float* bv = (const float*)d_in[6];
    const float* Wu = (const float*)d_in[7];
    const float* bu = (const float*)d_in[8];
    float* out = (float*)d_out;

    const int Nrows = in_sizes[0] / E;
    const int tiles = Nrows / TM;   // 2048

    cudaFuncSetAttribute(fused_sparse_attn,
                         cudaFuncAttributeMaxDynamicSharedMemorySize, SMEM_TOTAL);

    prep_qkv<<<(H * 3 * S * S + 255) / 256, 256>>>(Wq, Wk, Wv);
    prep_wu<<<(E * E + 255) / 256, 256>>>(Wu);
    fused_sparse_attn<<<tiles, 256, SMEM_TOTAL>>>(x, bq, bk, bv, bu, out);
}

// round 11
// speedup vs baseline: 1.0882x; 1.0882x over previous
#include <cuda_runtime.h>
#include <cuda_fp16.h>
#include <cstdint>

// ============================ problem constants ============================
constexpr int E = 512, H = 8, S = 64, TM = 64;

// ============================ device scratch (weights only) ================
// per head: {q_hi, k_hi, v_hi} 64x64 fp16 [s][t] SW128 tiles (8KB each) = 24KB/head
__device__ __align__(1024) unsigned char g_wqkv[H * 3 * 8192];
// Wu_hi chunks: bidx = nh*8 + kc -> [64k x 256n] fp16 swz512, 32KB each (512KB total)
__device__ __align__(1024) unsigned char g_wub[16 * 32768];

// ============================ helpers ======================================
__device__ __forceinline__ uint32_t smem_u32(const void* p) {
    uint32_t a;
    asm("{ .reg .u64 t; cvta.to.shared.u64 t, %1; cvt.u32.u64 %0, t; }" : "=r"(a) : "l"(p));
    return a;
}
__host__ __device__ __forceinline__ uint32_t swz128(uint32_t o) { return o ^ ((o >> 3) & 0x70); }
__host__ __device__ __forceinline__ uint32_t swz512(uint32_t o) { return o ^ ((o >> 5) & 0x70); }

__device__ __forceinline__ void ldsm_x4(uint32_t (&r)[4], uint32_t a) {
    asm volatile("ldmatrix.sync.aligned.m8n8.x4.shared.b16 {%0,%1,%2,%3}, [%4];"
        : "=r"(r[0]), "=r"(r[1]), "=r"(r[2]), "=r"(r[3]) : "r"(a));
}
__device__ __forceinline__ void ldsm_x4t(uint32_t (&r)[4], uint32_t a) {
    asm volatile("ldmatrix.sync.aligned.m8n8.x4.trans.shared.b16 {%0,%1,%2,%3}, [%4];"
        : "=r"(r[0]), "=r"(r[1]), "=r"(r[2]), "=r"(r[3]) : "r"(a));
}
__device__ __forceinline__ void mma16816(float (&d)[4], const uint32_t (&a)[4],
                                         uint32_t b0, uint32_t b1) {
    asm volatile("mma.sync.aligned.m16n8k16.row.col.f32.f16.f16.f32 "
        "{%0,%1,%2,%3}, {%4,%5,%6,%7}, {%8,%9}, {%0,%1,%2,%3};"
        : "+f"(d[0]), "+f"(d[1]), "+f"(d[2]), "+f"(d[3])
        : "r"(a[0]), "r"(a[1]), "r"(a[2]), "r"(a[3]), "r"(b0), "r"(b1));
}
__device__ __forceinline__ void cp16(uint32_t dst, const void* src) {
    asm volatile("cp.async.cg.shared.global [%0], [%1], 16;" :: "r"(dst), "l"(src));
}
#define CP_COMMIT() asm volatile("cp.async.commit_group;" ::: "memory")
#define CP_WAIT(n)  asm volatile("cp.async.wait_group %0;" :: "n"(n) : "memory")

__device__ __forceinline__ uint32_t pack2h(__half a, __half b) {
    __half2 p(a, b);
    return *reinterpret_cast<uint32_t*>(&p);
}
__device__ __forceinline__ uint32_t packf2(float2 v) {
    return pack2h(__float2half(v.x), __float2half(v.y));
}

// ============================ prep kernels =================================
// mats: 0=q_hi, 1=k_hi, 2=v_hi ; tile layout [s-rows][t-cols] fp16 SW128
__global__ void prep_qkv(const float* __restrict__ Wq, const float* __restrict__ Wk,
                         const float* __restrict__ Wv) {
    int idx = blockIdx.x * 256 + threadIdx.x;
    if (idx >= H * 3 * S * S) return;
    int h = idx / (3 * S * S);
    int mat = (idx >> 12) % 3;
    int s = (idx >> 6) & 63, t = idx & 63;
    const float* W = (mat == 0) ? Wq : ((mat == 1) ? Wk : Wv);
    float v = W[(h * S + s) * S + t];
    uint32_t off = swz128((uint32_t)(s * 128 + t * 2));
    *reinterpret_cast<__half*>(g_wqkv + (size_t)(h * 3 + mat) * 8192 + off) = __float2half(v);
}
// Wu_hi: chunk bidx = (n>>8)*8 + (k>>6): [64k x 256n] fp16 swz512
__global__ void prep_wu(const float* __restrict__ Wu) {
    int idx = blockIdx.x * 256 + threadIdx.x;
    if (idx >= E * E) return;
    int k = idx >> 9, n = idx & 511;
    int kc = k >> 6, kk = k & 63, nh = n >> 8, nn = n & 255;
    size_t base = (size_t)(nh * 8 + kc) * 32768;
    uint32_t off = swz512((uint32_t)(kk * 512 + nn * 2));
    *reinterpret_cast<__half*>(g_wub + base + off) = __float2half(Wu[idx]);
}

// ============================ fused kernel =================================
// smem map (bytes), 112KB total -> 2 CTAs/SM:
//   sT  @ 0     : 8 tiles [64r x 64k] fp16 SW128 (head h = k-chunk h) = 64KB
//   BUF @ 65536 : phase1 = W head-pair (48KB); phase2 = B 2 x 16KB sub-chunks
constexpr uint32_t ST = 0, BUF = 65536;
constexpr uint32_t SMEM_TOTAL = 114688;

__global__ __launch_bounds__(256, 2)
void fused_sparse_attn(const float* __restrict__ x,
                       const float* __restrict__ bq, const float* __restrict__ bk,
                       const float* __restrict__ bv,
                       const float* __restrict__ bu, float* __restrict__ out)
{
    extern __shared__ unsigned char smem[];
    const uint32_t sb = smem_u32(smem);
    const int tid = threadIdx.x, lane = tid & 31, wid = tid >> 5;
    const int row0 = blockIdx.x * TM;
    const float SC = 0.04419417382415922f;   // 1/sqrt(512)

    const int g  = lane >> 2;
    const int qd = lane & 3;
    const uint32_t hiSel = (uint32_t)((lane >> 4) << 4);

    // ===================== Phase 1: QKV + softmax -> sT ====================
    const int lh = wid >> 2;                  // local head in pair
    const int wm = wid & 3;                   // 16-row m position

    for (int hp = 0; hp < 4; ++hp) {
        // -- stage W head-pair (pre-swizzled, 48KB contiguous) --
        {
            const char* src = (const char*)g_wqkv + (size_t)hp * 49152;
            #pragma unroll
            for (int i = 0; i < 12; ++i) {
                uint32_t o = (uint32_t)(tid + i * 256) * 16;
                cp16(sb + BUF + o, src + o);
            }
            CP_COMMIT();
        }
        // -- A fragments straight from gmem (overlaps the cp.async W load) --
        uint32_t aF[4][4];
        {
            const float* xr0 = x + (size_t)(row0 + wm * 16 + g) * E + hp * 128 + lh * 64;
            const float* xr1 = xr0 + 8 * (size_t)E;
            #pragma unroll
            for (int ks = 0; ks < 4; ++ks) {
                int c = ks * 16 + qd * 2;
                aF[ks][0] = packf2(*reinterpret_cast<const float2*>(xr0 + c));
                aF[ks][1] = packf2(*reinterpret_cast<const float2*>(xr1 + c));
                aF[ks][2] = packf2(*reinterpret_cast<const float2*>(xr0 + c + 8));
                aF[ks][3] = packf2(*reinterpret_cast<const float2*>(xr1 + c + 8));
            }
        }
        CP_WAIT(0);
        __syncthreads();          // W(hp) visible to all warps

        const int h = hp * 2 + lh;
        const uint32_t wbase = sb + BUF + (uint32_t)lh * 24576;

        float aq[8][4], ak[8][4];
        #pragma unroll
        for (int nt = 0; nt < 8; ++nt)
            #pragma unroll
            for (int c = 0; c < 4; ++c) { aq[nt][c] = 0.f; ak[nt][c] = 0.f; }

        // pass A: q and k
        #pragma unroll
        for (int ks = 0; ks < 4; ++ks) {
            #pragma unroll
            for (int ntp = 0; ntp < 4; ++ntp) {
                uint32_t boff = swz128((uint32_t)(ks * 16 + (lane & 15)) * 128
                                       + (uint32_t)ntp * 32 + hiSel);
                uint32_t bQ[4], bK[4];
                ldsm_x4t(bQ, wbase + boff);
                ldsm_x4t(bK, wbase + 8192 + boff);
                mma16816(aq[2*ntp],   aF[ks], bQ[0], bQ[1]);
                mma16816(aq[2*ntp+1], aF[ks], bQ[2], bQ[3]);
                mma16816(ak[2*ntp],   aF[ks], bK[0], bK[1]);
                mma16816(ak[2*ntp+1], aF[ks], bK[2], bK[3]);
            }
        }
        // pass B: v
        float av[8][4];
        #pragma unroll
        for (int nt = 0; nt < 8; ++nt)
            #pragma unroll
            for (int c = 0; c < 4; ++c) av[nt][c] = 0.f;
        #pragma unroll
        for (int ks = 0; ks < 4; ++ks) {
            #pragma unroll
            for (int ntp = 0; ntp < 4; ++ntp) {
                uint32_t boff = swz128((uint32_t)(ks * 16 + (lane & 15)) * 128
                                       + (uint32_t)ntp * 32 + hiSel);
                uint32_t bV[4];
                ldsm_x4t(bV, wbase + 16384 + boff);
                mma16816(av[2*ntp],   aF[ks], bV[0], bV[1]);
                mma16816(av[2*ntp+1], aF[ks], bV[2], bV[3]);
            }
        }

        // -- softmax (quad-local), reuse aq<-e, av<-v+bias --
        const float* bqh = bq + h * S;
        const float* bkh = bk + h * S;
        const float* bvh = bv + h * S;
        float ssum0 = 0.f, ssum1 = 0.f;
        #pragma unroll
        for (int nt = 0; nt < 8; ++nt) {
            int col0 = nt * 8 + qd * 2;
            float2 b1 = *reinterpret_cast<const float2*>(bqh + col0);
            float2 b2 = *reinterpret_cast<const float2*>(bkh + col0);
            float2 b3 = *reinterpret_cast<const float2*>(bvh + col0);
            float e;
            e = __expf((aq[nt][0] + b1.x) * (ak[nt][0] + b2.x) * SC); aq[nt][0] = e; ssum0 += e;
            e = __expf((aq[nt][1] + b1.y) * (ak[nt][1] + b2.y) * SC); aq[nt][1] = e; ssum0 += e;
            e = __expf((aq[nt][2] + b1.x) * (ak[nt][2] + b2.x) * SC); aq[nt][2] = e; ssum1 += e;
            e = __expf((aq[nt][3] + b1.y) * (ak[nt][3] + b2.y) * SC); aq[nt][3] = e; ssum1 += e;
            av[nt][0] += b3.x; av[nt][1] += b3.y;
            av[nt][2] += b3.x; av[nt][3] += b3.y;
        }
        ssum0 += __shfl_xor_sync(0xffffffffu, ssum0, 1);
        ssum0 += __shfl_xor_sync(0xffffffffu, ssum0, 2);
        ssum1 += __shfl_xor_sync(0xffffffffu, ssum1, 1);
        ssum1 += __shfl_xor_sync(0xffffffffu, ssum1, 2);
        const float inv0 = 1.0f / ssum0, inv1 = 1.0f / ssum1;

        {
            int rt0 = wm * 16 + g;
            #pragma unroll
            for (int nt = 0; nt < 8; ++nt) {
                uint32_t cb = (uint32_t)((nt * 8 + qd * 2) * 2);
                uint32_t offBase = (uint32_t)h * 8192;
                float t0 = aq[nt][0] * inv0 * av[nt][0];
                float t1 = aq[nt][1] * inv0 * av[nt][1];
                float t2 = aq[nt][2] * inv1 * av[nt][2];
                float t3 = aq[nt][3] * inv1 * av[nt][3];
                *reinterpret_cast<uint32_t*>(smem + ST + offBase
                    + swz128((uint32_t)rt0 * 128 + cb)) =
                    pack2h(__float2half(t0), __float2half(t1));
                *reinterpret_cast<uint32_t*>(smem + ST + offBase
                    + swz128((uint32_t)(rt0 + 8) * 128 + cb)) =
                    pack2h(__float2half(t2), __float2half(t3));
            }
        }
        __syncthreads();   // BUF (W) safe to overwrite; sT coherent after last hp
    }

    // ===================== Phase 2: out = t @ Wu_hi + bu ===================
    // warp = 64 rows x 32 cols (pn = wid): B read exactly once -> crossbar unbound
    const int pn = wid;

    // B sub-chunk: step s (0..31): nh=s>>4, kc=(s>>1)&7, half=s&1 -> 16KB contiguous
    auto load_sub = [&](int s, int buf) {
        int nh = s >> 4, kc = (s >> 1) & 7, half = s & 1;
        const char* src = (const char*)g_wub + (size_t)(nh * 8 + kc) * 32768
                        + (size_t)half * 16384;
        uint32_t d = sb + BUF + (uint32_t)buf * 16384;
        #pragma unroll
        for (int i = 0; i < 4; ++i) {
            uint32_t o = (uint32_t)(tid + i * 256) * 16;
            cp16(d + o, src + o);
        }
    };

    load_sub(0, 0);
    CP_COMMIT();

    for (int nh = 0; nh < 2; ++nh) {
        float acc[16][4];   // [mf*4 + nf][..] : 4 m16 frags x 4 n8 frags
        #pragma unroll
        for (int nf = 0; nf < 16; ++nf)
            #pragma unroll
            for (int c = 0; c < 4; ++c) acc[nf][c] = 0.f;

        for (int s16 = 0; s16 < 16; ++s16) {
            int s = nh * 16 + s16;
            CP_WAIT(0);
            __syncthreads();
            if (s + 1 < 32) { load_sub(s + 1, (s + 1) & 1); CP_COMMIT(); }

            int kc = s16 >> 1, half = s16 & 1;
            uint32_t bb = sb + BUF + (uint32_t)(s & 1) * 16384;
            uint32_t tA = sb + ST + (uint32_t)kc * 8192;
            #pragma unroll
            for (int ksg = 0; ksg < 2; ++ksg) {
                uint32_t kOff = (uint32_t)(half * 64 + ksg * 32) + hiSel;
                uint32_t a[4][4];
                #pragma unroll
                for (int mf = 0; mf < 4; ++mf)
                    ldsm_x4(a[mf], tA + swz128((uint32_t)(mf * 16 + (lane & 15)) * 128 + kOff));
                #pragma unroll
                for (int ntp = 0; ntp < 2; ++ntp) {
                    uint32_t boff = swz512((uint32_t)(ksg * 16 + (lane & 15)) * 512
                                           + (uint32_t)(pn * 64 + ntp * 32) + hiSel);
                    uint32_t b[4];
                    ldsm_x4t(b, bb + boff);
                    #pragma unroll
                    for (int mf = 0; mf < 4; ++mf) {
                        mma16816(acc[mf * 4 + ntp * 2],     a[mf], b[0], b[1]);
                        mma16816(acc[mf * 4 + ntp * 2 + 1], a[mf], b[2], b[3]);
                    }
                }
            }
        }

        // epilogue for this N-half
        #pragma unroll
        for (int mf = 0; mf < 4; ++mf) {
            int r0 = row0 + mf * 16 + g;
            #pragma unroll
            for (int nf = 0; nf < 4; ++nf) {
                int col0 = nh * 256 + pn * 32 + nf * 8 + qd * 2;
                float2 bb2 = *reinterpret_cast<const float2*>(bu + col0);
                const float* a = acc[mf * 4 + nf];
                float2 o0 = make_float2(a[0] + bb2.x, a[1] + bb2.y);
                float2 o1 = make_float2(a[2] + bb2.x, a[3] + bb2.y);
                *reinterpret_cast<float2*>(out + (size_t)r0 * E + col0)       = o0;
                *reinterpret_cast<float2*>(out + (size_t)(r0 + 8) * E + col0) = o1;
            }
        }
    }
}

// ============================ launch =======================================
extern "C" void kernel_launch(void* const* d_in, const int* in_sizes, int n_in,
                              void* d_out, int out_size)
{
    const float* x  = (const float*)d_in[0];
    const float* Wq = (const float*)d_in[1];
    const float* bq = (const float*)d_in[2];
    const float* Wk = (const float*)d_in[3];
    const float* bk = (const float*)d_in[4];
    const float* Wv = (const float*)d_in[5];
    const float* bv = (const float*)d_in[6];
    const float* Wu = (const float*)d_in[7];
    const float* bu = (const float*)d_in[8];
    float* out = (float*)d_out;

    const int Nrows = in_sizes[0] / E;
    const int tiles = Nrows / TM;   // 2048

    cudaFuncSetAttribute(fused_sparse_attn,
                         cudaFuncAttributeMaxDynamicSharedMemorySize, SMEM_TOTAL);

    prep_qkv<<<(H * 3 * S * S + 255) / 256, 256>>>(Wq, Wk, Wv);
    prep_wu<<<(E * E + 255) / 256, 256>>>(Wu);
    fused_sparse_attn<<<tiles, 256, SMEM_TOTAL>>>(x, bq, bk, bv, bu, out);
}